// round 3
// baseline (speedup 1.0000x reference)
#include <cuda_runtime.h>

typedef unsigned long long u64;

#define BM 128
#define BN 128
#define BK 16
#define NTHREADS 256

// anchors per level: {aw0,ah0,aw1,ah1,aw2,ah2}
__constant__ float g_anch[3][6] = {
    {10.f, 13.f, 16.f, 30.f, 33.f, 23.f},
    {30.f, 61.f, 62.f, 45.f, 59.f, 119.f},
    {116.f, 90.f, 156.f, 198.f, 373.f, 326.f}
};

__device__ __forceinline__ u64 dup2(float x) {
    u64 r;
    asm("mov.b64 %0, {%1, %1};" : "=l"(r) : "f"(x));
    return r;
}
__device__ __forceinline__ void fma2(u64 &c, u64 a, u64 b) {
    asm("fma.rn.f32x2 %0, %1, %2, %0;" : "+l"(c) : "l"(a), "l"(b));
}
__device__ __forceinline__ float2 unpk(u64 v) {
    float lo, hi;
    asm("mov.b64 {%0, %1}, %2;" : "=f"(lo), "=f"(hi) : "l"(v));
    return make_float2(lo, hi);
}
__device__ __forceinline__ float sigm(float x) { return 1.f / (1.f + __expf(-x)); }

// One GEMM tile (BM x BN) of P = W (267 x C) * X_b (C x HW), fused decode epilogue.
// Accumulators are f32x2-packed along M: acc[ip][j] holds rows (mbase+2ip, mbase+2ip+1), col j.
template<int C, int HW, int NX>
__device__ __forceinline__ void level_gemm(
    const float* __restrict__ X, const float* __restrict__ W,
    float* __restrict__ Out,
    float (&As)[BK][BM + 4], float (&Bs)[BK][BN], const float* sBias,
    int bat, int mt, int nt, float stride_px, int lvl, int loff)
{
    const int tid = threadIdx.x;
    const int tm = tid >> 4;        // 0..15 -> 8 M rows each
    const int tn = tid & 15;        // 0..15 -> 8 N cols each
    const int m0 = mt * BM;
    const int n0 = nt * BN;
    const float* Xb = X + (size_t)bat * C * HW;

    u64 acc[4][8];
#pragma unroll
    for (int i = 0; i < 4; ++i)
#pragma unroll
        for (int j = 0; j < 8; ++j) acc[i][j] = 0ull;

    // tile-load assignments
    const int wm = tid >> 1;              // 0..127 : M row of W tile
    const int wk = (tid & 1) * 8;         // 0 or 8 : k offset (8 floats)
    const int xr = tid >> 4;              // 0..15  : k row of X tile
    const int xc = (tid & 15) * 8;        // 0..120 : n offset (8 floats)
    const int gm = m0 + wm;
    const int gn = n0 + xc;

    for (int k0 = 0; k0 < C; k0 += BK) {
        float4 w0v = make_float4(0.f, 0.f, 0.f, 0.f), w1v = w0v;
        if (gm < 267) {
            const float* wp = W + (size_t)gm * C + (k0 + wk);
            w0v = *(const float4*)wp;
            w1v = *(const float4*)(wp + 4);
        }
        float4 x0v = make_float4(0.f, 0.f, 0.f, 0.f), x1v = x0v;
        if (gn < HW) {  // gn multiple of 8, HW multiple of 8 -> whole 8-float run in-bounds
            const float* xp = Xb + (size_t)(k0 + xr) * HW + gn;
            x0v = *(const float4*)xp;
            x1v = *(const float4*)(xp + 4);
        }
        // store W transposed: As[k][m]
        As[wk + 0][wm] = w0v.x; As[wk + 1][wm] = w0v.y;
        As[wk + 2][wm] = w0v.z; As[wk + 3][wm] = w0v.w;
        As[wk + 4][wm] = w1v.x; As[wk + 5][wm] = w1v.y;
        As[wk + 6][wm] = w1v.z; As[wk + 7][wm] = w1v.w;
        *(float4*)&Bs[xr][xc]     = x0v;
        *(float4*)&Bs[xr][xc + 4] = x1v;
        __syncthreads();

#pragma unroll
        for (int k = 0; k < BK; ++k) {
            const float* ap = &As[k][tm * 8];           // 16B aligned (pad=4)
            ulonglong2 aa = *(const ulonglong2*)ap;     // rows m..m+3 as 2 packed pairs
            ulonglong2 ab = *(const ulonglong2*)(ap + 4);
            float4 bq0 = *(const float4*)&Bs[k][tn * 8];
            float4 bq1 = *(const float4*)&Bs[k][tn * 8 + 4];
            float bf[8] = {bq0.x, bq0.y, bq0.z, bq0.w, bq1.x, bq1.y, bq1.z, bq1.w};
#pragma unroll
            for (int j = 0; j < 8; ++j) {
                u64 bd = dup2(bf[j]);
                fma2(acc[0][j], aa.x, bd);
                fma2(acc[1][j], aa.y, bd);
                fma2(acc[2][j], ab.x, bd);
                fma2(acc[3][j], ab.y, bd);
            }
        }
        __syncthreads();
    }

    // ---- fused decode epilogue ----
    const int mbase = m0 + tm * 8;
#pragma unroll
    for (int ip = 0; ip < 4; ++ip) {
#pragma unroll
        for (int h = 0; h < 2; ++h) {
            const int o = mbase + ip * 2 + h;
            if (o >= 267) continue;
            const int ai = o / 89;
            const int e  = o - ai * 89;
            const float bv = sBias[o];
            float anc = 0.f;
            if (e == 2) anc = g_anch[lvl][ai * 2];
            if (e == 3) anc = g_anch[lvl][ai * 2 + 1];
            const size_t rowbase = (size_t)bat * 25200 + (size_t)loff + (size_t)ai * HW;
#pragma unroll
            for (int j = 0; j < 8; ++j) {
                const int n = n0 + tn * 8 + j;
                if (HW % BN != 0) { if (n >= HW) continue; }
                float2 p = unpk(acc[ip][j]);
                float v = (h ? p.y : p.x) + bv;
                float res;
                if (e == 0)              res = (sigm(v) + (float)(n % NX)) * stride_px;
                else if (e == 1)         res = (sigm(v) + (float)(n / NX)) * stride_px;
                else if (e == 2 || e == 3) res = __expf(v) * anc;
                else                     res = sigm(v);
                Out[(rowbase + (size_t)n) * 89 + e] = res;
            }
        }
    }
}

// Level tile counts along N: L0: 6400/128=50, L1: ceil(1600/128)=13, L2: ceil(400/128)=4 -> 67
__global__ void __launch_bounds__(NTHREADS, 2)
detect_fused(const float* __restrict__ x0, const float* __restrict__ w0, const float* __restrict__ b0,
             const float* __restrict__ x1, const float* __restrict__ w1, const float* __restrict__ b1,
             const float* __restrict__ x2, const float* __restrict__ w2, const float* __restrict__ b2,
             float* __restrict__ out)
{
    __shared__ float As[BK][BM + 4];
    __shared__ float Bs[BK][BN];
    __shared__ float sBias[272];

    const int bat = blockIdx.z;
    const int mt  = blockIdx.y;
    const int xt  = blockIdx.x;

    const float* bias = (xt < 50) ? b0 : ((xt < 63) ? b1 : b2);
    for (int i = threadIdx.x; i < 272; i += NTHREADS)
        sBias[i] = (i < 267) ? bias[i] : 0.f;
    // first __syncthreads inside level_gemm orders sBias before its epilogue use

    if (xt < 50)
        level_gemm<256, 6400, 80>(x0, w0, out, As, Bs, sBias, bat, mt, xt,       8.f, 0, 0);
    else if (xt < 63)
        level_gemm<512, 1600, 40>(x1, w1, out, As, Bs, sBias, bat, mt, xt - 50, 16.f, 1, 19200);
    else
        level_gemm<1024, 400, 20>(x2, w2, out, As, Bs, sBias, bat, mt, xt - 63, 32.f, 2, 24000);
}

extern "C" void kernel_launch(void* const* d_in, const int* in_sizes, int n_in,
                              void* d_out, int out_size)
{
    // Resolve inputs by element count (robust to metadata ordering).
    const float *x0 = 0, *x1 = 0, *x2 = 0, *w0 = 0, *w1 = 0, *w2 = 0;
    const float* bs[3] = {0, 0, 0};
    int nb = 0;
    for (int i = 0; i < n_in; ++i) {
        const float* p = (const float*)d_in[i];
        switch (in_sizes[i]) {
            case 13107200: x0 = p; break;  // 8*256*80*80
            case 6553600:  x1 = p; break;  // 8*512*40*40
            case 3276800:  x2 = p; break;  // 8*1024*20*20
            case 68352:    w0 = p; break;  // 267*256
            case 136704:   w1 = p; break;  // 267*512
            case 273408:   w2 = p; break;  // 267*1024
            case 267:      if (nb < 3) bs[nb++] = p; break;  // b0, b1, b2 in order
            default: break;
        }
    }
    dim3 grid(67, 3, 8);
    dim3 block(NTHREADS);
    detect_fused<<<grid, block>>>(x0, w0, bs[0], x1, w1, bs[1], x2, w2, bs[2],
                                  (float*)d_out);
}

// round 5
// speedup vs baseline: 2.4855x; 2.4855x over previous
#include <cuda_runtime.h>
#include <cstdint>

#define NTH 256

__constant__ float g_anch[3][6] = {
    {10.f, 13.f, 16.f, 30.f, 33.f, 23.f},
    {30.f, 61.f, 62.f, 45.f, 59.f, 119.f},
    {116.f, 90.f, 156.f, 198.f, 373.f, 326.f}
};

__device__ __forceinline__ uint32_t f2tf(float f) {
    uint32_t u;
    asm("cvt.rna.tf32.f32 %0, %1;" : "=r"(u) : "f"(f));
    return u;
}
__device__ __forceinline__ float sigm(float x) { return 1.f / (1.f + __expf(-x)); }

__device__ __forceinline__ void mma_tf32(float* c, const uint32_t* a, const uint32_t* b) {
    asm volatile(
        "mma.sync.aligned.m16n8k8.row.col.f32.tf32.tf32.f32 "
        "{%0,%1,%2,%3}, {%4,%5,%6,%7}, {%8,%9}, {%0,%1,%2,%3};"
        : "+f"(c[0]), "+f"(c[1]), "+f"(c[2]), "+f"(c[3])
        : "r"(a[0]), "r"(a[1]), "r"(a[2]), "r"(a[3]), "r"(b[0]), "r"(b[1]));
}

// smem strides chosen for conflict-free fragment LDS:
//  Ws[m][k]: stride 20 words -> bank shift 20 per row; lanes (g,t4) hit 32 distinct banks
//  Bs[k][n]: stride 136 words -> bank shift 8 per row; 8*t4+g distinct
#define WS_STRIDE 20
#define BS_STRIDE 136

template<int C, int HW, int NX>
__device__ __forceinline__ void run_level(
    const float* __restrict__ X, const float* __restrict__ W,
    const float* __restrict__ Bias, float* __restrict__ Out,
    int bat, int mt, int nt, float stride_px, int lvl, int loff,
    uint32_t (&Ws)[128][WS_STRIDE], uint32_t (&Bs)[16][BS_STRIDE], float* sBias)
{
    const int tid  = threadIdx.x;
    const int wid  = tid >> 5;
    const int lane = tid & 31;
    const int g    = lane >> 2;   // groupID
    const int t4   = lane & 3;    // threadID_in_group
    const int wm   = (wid & 1) * 64;   // warp M offset within tile
    const int wn   = (wid >> 1) * 32;  // warp N offset within tile
    const int m0   = mt * 128;
    const int n0   = nt * 128;
    const float* Xb = X + (size_t)bat * C * HW;

    for (int i = tid; i < 267; i += NTH) sBias[i] = Bias[i];

    float acc[4][4][4];
#pragma unroll
    for (int a = 0; a < 4; ++a)
#pragma unroll
        for (int b = 0; b < 4; ++b)
#pragma unroll
            for (int k = 0; k < 4; ++k) acc[a][b][k] = 0.f;

    // loader lane assignments
    const int wRow = tid >> 1;           // 0..127 : W tile m row
    const int wPair = (tid & 1) * 8;     // 0/8    : k offset
    const int xN = (tid & 31) * 4;       // 0..124 : X tile n offset
    const int xK = tid >> 5;             // 0..7   : X tile k row (and +8)
    const bool wIn = (m0 + wRow) < 267;
    const bool xIn = (n0 + xN) < HW;

    float4 wa, wb, xa, xb;
    const float4 z4 = make_float4(0.f, 0.f, 0.f, 0.f);

    // prefetch chunk 0
    {
        const float* wp = W + (size_t)(m0 + wRow) * C + wPair;
        wa = wIn ? *(const float4*)wp : z4;
        wb = wIn ? *(const float4*)(wp + 4) : z4;
        const float* xp = Xb + (size_t)xK * HW + n0 + xN;
        xa = xIn ? *(const float4*)xp : z4;
        xb = xIn ? *(const float4*)(xp + (size_t)8 * HW) : z4;
    }

    const int NCH = C / 16;
    for (int i = 0; i < NCH; ++i) {
        if (i) __syncthreads();   // previous compute done before overwrite
        // store (with tf32 rounding)
        {
            uint4 u;
            u.x = f2tf(wa.x); u.y = f2tf(wa.y); u.z = f2tf(wa.z); u.w = f2tf(wa.w);
            *(uint4*)&Ws[wRow][wPair] = u;
            u.x = f2tf(wb.x); u.y = f2tf(wb.y); u.z = f2tf(wb.z); u.w = f2tf(wb.w);
            *(uint4*)&Ws[wRow][wPair + 4] = u;
            u.x = f2tf(xa.x); u.y = f2tf(xa.y); u.z = f2tf(xa.z); u.w = f2tf(xa.w);
            *(uint4*)&Bs[xK][xN] = u;
            u.x = f2tf(xb.x); u.y = f2tf(xb.y); u.z = f2tf(xb.z); u.w = f2tf(xb.w);
            *(uint4*)&Bs[xK + 8][xN] = u;
        }
        __syncthreads();

        // prefetch next chunk (overlaps compute below)
        if (i + 1 < NCH) {
            const int k0 = (i + 1) * 16;
            const float* wp = W + (size_t)(m0 + wRow) * C + k0 + wPair;
            wa = wIn ? *(const float4*)wp : z4;
            wb = wIn ? *(const float4*)(wp + 4) : z4;
            const float* xp = Xb + (size_t)(k0 + xK) * HW + n0 + xN;
            xa = xIn ? *(const float4*)xp : z4;
            xb = xIn ? *(const float4*)(xp + (size_t)8 * HW) : z4;
        }

        // compute: 2 k8 steps
#pragma unroll
        for (int kk = 0; kk < 16; kk += 8) {
            uint32_t afr[4][4];
#pragma unroll
            for (int ma = 0; ma < 4; ++ma) {
                const int mr = wm + ma * 16 + g;
                afr[ma][0] = Ws[mr][kk + t4];
                afr[ma][1] = Ws[mr + 8][kk + t4];
                afr[ma][2] = Ws[mr][kk + t4 + 4];
                afr[ma][3] = Ws[mr + 8][kk + t4 + 4];
            }
            uint32_t bfr[4][2];
#pragma unroll
            for (int na = 0; na < 4; ++na) {
                const int nc = wn + na * 8 + g;
                bfr[na][0] = Bs[kk + t4][nc];
                bfr[na][1] = Bs[kk + t4 + 4][nc];
            }
#pragma unroll
            for (int ma = 0; ma < 4; ++ma)
#pragma unroll
                for (int na = 0; na < 4; ++na)
                    mma_tf32(acc[ma][na], afr[ma], bfr[na]);
        }
    }

    // ---- fused decode epilogue ----
#pragma unroll
    for (int ma = 0; ma < 4; ++ma) {
#pragma unroll
        for (int half = 0; half < 2; ++half) {
            const int m = m0 + wm + ma * 16 + g + half * 8;
            if (m >= 267) continue;
            const int ai = m / 89;
            const int e  = m - ai * 89;
            const float bv = sBias[m];
            const float anc = (e == 2) ? g_anch[lvl][ai * 2]
                            : (e == 3) ? g_anch[lvl][ai * 2 + 1] : 0.f;
            const size_t rowbase = (size_t)bat * 25200 + (size_t)loff + (size_t)ai * HW;
#pragma unroll
            for (int na = 0; na < 4; ++na) {
#pragma unroll
                for (int c = 0; c < 2; ++c) {
                    const int n = n0 + wn + na * 8 + t4 * 2 + c;
                    if (HW % 128 != 0) { if (n >= HW) continue; }
                    const float v = acc[ma][na][half * 2 + c] + bv;
                    float res;
                    if (e == 0)      res = (sigm(v) + (float)(n % NX)) * stride_px;
                    else if (e == 1) res = (sigm(v) + (float)(n / NX)) * stride_px;
                    else if (e < 4)  res = __expf(v) * anc;
                    else             res = sigm(v);
                    Out[(rowbase + (size_t)n) * 89 + e] = res;
                }
            }
        }
    }
}

// N tiles: L0 50, L1 13 (last partial), L2 4 (last partial) -> 67
__global__ void __launch_bounds__(NTH, 2)
detect_mma(const float* __restrict__ x0, const float* __restrict__ w0, const float* __restrict__ b0,
           const float* __restrict__ x1, const float* __restrict__ w1, const float* __restrict__ b1,
           const float* __restrict__ x2, const float* __restrict__ w2, const float* __restrict__ b2,
           float* __restrict__ out)
{
    __shared__ uint32_t Ws[128][WS_STRIDE];
    __shared__ uint32_t Bs[16][BS_STRIDE];
    __shared__ float sBias[267];

    const int xt  = blockIdx.x;
    const int mt  = blockIdx.y;
    const int bat = blockIdx.z;

    if (xt < 50)
        run_level<256, 6400, 80>(x0, w0, b0, out, bat, mt, xt,       8.f, 0, 0,     Ws, Bs, sBias);
    else if (xt < 63)
        run_level<512, 1600, 40>(x1, w1, b1, out, bat, mt, xt - 50, 16.f, 1, 19200, Ws, Bs, sBias);
    else
        run_level<1024, 400, 20>(x2, w2, b2, out, bat, mt, xt - 63, 32.f, 2, 24000, Ws, Bs, sBias);
}

extern "C" void kernel_launch(void* const* d_in, const int* in_sizes, int n_in,
                              void* d_out, int out_size)
{
    const float *x0 = 0, *x1 = 0, *x2 = 0, *w0 = 0, *w1 = 0, *w2 = 0;
    const float* bs[3] = {0, 0, 0};
    int nb = 0;
    for (int i = 0; i < n_in; ++i) {
        const float* p = (const float*)d_in[i];
        switch (in_sizes[i]) {
            case 13107200: x0 = p; break;
            case 6553600:  x1 = p; break;
            case 3276800:  x2 = p; break;
            case 68352:    w0 = p; break;
            case 136704:   w1 = p; break;
            case 273408:   w2 = p; break;
            case 267:      if (nb < 3) bs[nb++] = p; break;
            default: break;
        }
    }
    dim3 grid(67, 3, 8);
    detect_mma<<<grid, NTH>>>(x0, w0, bs[0], x1, w1, bs[1], x2, w2, bs[2], (float*)d_out);
}

// round 6
// speedup vs baseline: 2.7191x; 1.0940x over previous
#include <cuda_runtime.h>
#include <cstdint>

#define NTH 256
#define STAGES 3

__constant__ float g_anch[3][6] = {
    {10.f, 13.f, 16.f, 30.f, 33.f, 23.f},
    {30.f, 61.f, 62.f, 45.f, 59.f, 119.f},
    {116.f, 90.f, 156.f, 198.f, 373.f, 326.f}
};

__device__ __forceinline__ float sigm(float x) { return 1.f / (1.f + __expf(-x)); }

__device__ __forceinline__ void mma_tf32(float* c, const uint32_t* a, const uint32_t* b) {
    asm volatile(
        "mma.sync.aligned.m16n8k8.row.col.f32.tf32.tf32.f32 "
        "{%0,%1,%2,%3}, {%4,%5,%6,%7}, {%8,%9}, {%0,%1,%2,%3};"
        : "+f"(c[0]), "+f"(c[1]), "+f"(c[2]), "+f"(c[3])
        : "r"(a[0]), "r"(a[1]), "r"(a[2]), "r"(a[3]), "r"(b[0]), "r"(b[1]));
}

__device__ __forceinline__ void cp16(uint32_t saddr, const void* gptr, uint32_t sz) {
    asm volatile("cp.async.cg.shared.global [%0], [%1], 16, %2;"
                 :: "r"(saddr), "l"(gptr), "r"(sz) : "memory");
}
#define CP_COMMIT() asm volatile("cp.async.commit_group;" ::: "memory")
#define CP_WAIT1()  asm volatile("cp.async.wait_group 1;" ::: "memory")

// smem strides (words): conflict-free fragment LDS
#define WS_STRIDE 20     // Ws[m][k]
#define BS_STRIDE 136    // Bs[k][n]
#define WS_WORDS (128 * WS_STRIDE)   // 2560
#define BS_WORDS (16 * BS_STRIDE)    // 2176
#define DYN_WORDS (STAGES * (WS_WORDS + BS_WORDS) + 268)

template<int C, int HW, int NX>
__device__ __forceinline__ void run_level(
    const float* __restrict__ X, const float* __restrict__ W,
    const float* __restrict__ Bias, float* __restrict__ Out,
    int bat, int mt, int nt, float stride_px, int lvl, int loff)
{
    extern __shared__ uint32_t sh[];
    uint32_t* WsBase = sh;                                   // [STAGES][128][20]
    uint32_t* BsBase = sh + STAGES * WS_WORDS;               // [STAGES][16][136]
    float* sBias = (float*)(sh + STAGES * (WS_WORDS + BS_WORDS));

    const int tid  = threadIdx.x;
    const int wid  = tid >> 5;
    const int lane = tid & 31;
    const int g    = lane >> 2;
    const int t4   = lane & 3;
    const int wm   = (wid & 1) * 64;
    const int wn   = (wid >> 1) * 32;
    const int m0   = mt * 128;
    const int n0   = nt * 128;
    const float* Xb = X + (size_t)bat * C * HW;

    for (int i = tid; i < 267; i += NTH) sBias[i] = Bias[i];

    // loader assignments
    const int wRow  = tid >> 1;          // 0..127
    const int wPair = (tid & 1) * 8;     // 0 or 8
    const int xN    = (tid & 31) * 4;    // 0..124
    const int xK    = tid >> 5;          // 0..7 (and +8)
    const uint32_t wSz = ((m0 + wRow) < 267) ? 16u : 0u;
    const uint32_t xSz = ((n0 + xN) < HW) ? 16u : 0u;
    const float* wpB = W + (size_t)((m0 + wRow) < 267 ? (m0 + wRow) : 0) * C + wPair;
    const float* xpB = Xb + (size_t)xK * HW + ((n0 + xN) < HW ? (n0 + xN) : 0);

    uint32_t wsAddr[STAGES], bsAddr[STAGES];
#pragma unroll
    for (int s = 0; s < STAGES; ++s) {
        wsAddr[s] = (uint32_t)__cvta_generic_to_shared(WsBase + s * WS_WORDS + wRow * WS_STRIDE + wPair);
        bsAddr[s] = (uint32_t)__cvta_generic_to_shared(BsBase + s * BS_WORDS + xK * BS_STRIDE + xN);
    }

    const int NCH = C / 16;
    // prologue: issue chunks 0, 1
#pragma unroll
    for (int s = 0; s < STAGES - 1; ++s) {
        cp16(wsAddr[s],      wpB + (size_t)s * 16, wSz);
        cp16(wsAddr[s] + 16, wpB + (size_t)s * 16 + 4, wSz);
        cp16(bsAddr[s],                      xpB + (size_t)s * 16 * HW, xSz);
        cp16(bsAddr[s] + 8 * BS_STRIDE * 4,  xpB + (size_t)(s * 16 + 8) * HW, xSz);
        CP_COMMIT();
    }

    float acc[4][4][4];
#pragma unroll
    for (int a = 0; a < 4; ++a)
#pragma unroll
        for (int b = 0; b < 4; ++b)
#pragma unroll
            for (int k = 0; k < 4; ++k) acc[a][b][k] = 0.f;

    int s = 0;
    for (int i = 0; i < NCH; ++i) {
        CP_WAIT1();
        __syncthreads();

        const uint32_t* Wst = WsBase + s * WS_WORDS;
        const uint32_t* Bst = BsBase + s * BS_WORDS;

        // issue chunk i+2 into buffer (s+2)%3 (all threads already past compute of chunk i-1)
        const int ch = i + STAGES - 1;
        const int sn = (s + STAGES - 1 >= STAGES) ? s - 1 : s + STAGES - 1;
        if (ch < NCH) {
            cp16(wsAddr[sn],      wpB + (size_t)ch * 16, wSz);
            cp16(wsAddr[sn] + 16, wpB + (size_t)ch * 16 + 4, wSz);
            cp16(bsAddr[sn],                     xpB + (size_t)ch * 16 * HW, xSz);
            cp16(bsAddr[sn] + 8 * BS_STRIDE * 4, xpB + (size_t)(ch * 16 + 8) * HW, xSz);
        }
        CP_COMMIT();

#pragma unroll
        for (int kk = 0; kk < 16; kk += 8) {
            uint32_t afr[4][4];
#pragma unroll
            for (int ma = 0; ma < 4; ++ma) {
                const int mr = wm + ma * 16 + g;
                afr[ma][0] = Wst[mr * WS_STRIDE + kk + t4];
                afr[ma][1] = Wst[(mr + 8) * WS_STRIDE + kk + t4];
                afr[ma][2] = Wst[mr * WS_STRIDE + kk + t4 + 4];
                afr[ma][3] = Wst[(mr + 8) * WS_STRIDE + kk + t4 + 4];
            }
            uint32_t bfr[4][2];
#pragma unroll
            for (int na = 0; na < 4; ++na) {
                const int nc = wn + na * 8 + g;
                bfr[na][0] = Bst[(kk + t4) * BS_STRIDE + nc];
                bfr[na][1] = Bst[(kk + t4 + 4) * BS_STRIDE + nc];
            }
#pragma unroll
            for (int ma = 0; ma < 4; ++ma)
#pragma unroll
                for (int na = 0; na < 4; ++na)
                    mma_tf32(acc[ma][na], afr[ma], bfr[na]);
        }
        s = (s + 1 == STAGES) ? 0 : s + 1;
    }

    // ---- fused decode epilogue ----
#pragma unroll
    for (int ma = 0; ma < 4; ++ma) {
#pragma unroll
        for (int half = 0; half < 2; ++half) {
            const int m = m0 + wm + ma * 16 + g + half * 8;
            if (m >= 267) continue;
            const int ai = m / 89;
            const int e  = m - ai * 89;
            const float bv = sBias[m];
            const float anc = (e == 2) ? g_anch[lvl][ai * 2]
                            : (e == 3) ? g_anch[lvl][ai * 2 + 1] : 0.f;
            const size_t rowbase = (size_t)bat * 25200 + (size_t)loff + (size_t)ai * HW;
#pragma unroll
            for (int na = 0; na < 4; ++na) {
#pragma unroll
                for (int c = 0; c < 2; ++c) {
                    const int n = n0 + wn + na * 8 + t4 * 2 + c;
                    if (HW % 128 != 0) { if (n >= HW) continue; }
                    const float v = acc[ma][na][half * 2 + c] + bv;
                    float res;
                    if (e == 0)      res = (sigm(v) + (float)(n % NX)) * stride_px;
                    else if (e == 1) res = (sigm(v) + (float)(n / NX)) * stride_px;
                    else if (e < 4)  res = __expf(v) * anc;
                    else             res = sigm(v);
                    Out[(rowbase + (size_t)n) * 89 + e] = res;
                }
            }
        }
    }
}

// N tiles: L0 50, L1 13 (last partial), L2 4 (last partial) -> 67
__global__ void __launch_bounds__(NTH, 2)
detect_mma(const float* __restrict__ x0, const float* __restrict__ w0, const float* __restrict__ b0,
           const float* __restrict__ x1, const float* __restrict__ w1, const float* __restrict__ b1,
           const float* __restrict__ x2, const float* __restrict__ w2, const float* __restrict__ b2,
           float* __restrict__ out)
{
    const int xt  = blockIdx.x;
    const int mt  = blockIdx.y;
    const int bat = blockIdx.z;

    if (xt < 50)
        run_level<256, 6400, 80>(x0, w0, b0, out, bat, mt, xt,       8.f, 0, 0);
    else if (xt < 63)
        run_level<512, 1600, 40>(x1, w1, b1, out, bat, mt, xt - 50, 16.f, 1, 19200);
    else
        run_level<1024, 400, 20>(x2, w2, b2, out, bat, mt, xt - 63, 32.f, 2, 24000);
}

extern "C" void kernel_launch(void* const* d_in, const int* in_sizes, int n_in,
                              void* d_out, int out_size)
{
    const float *x0 = 0, *x1 = 0, *x2 = 0, *w0 = 0, *w1 = 0, *w2 = 0;
    const float* bs[3] = {0, 0, 0};
    int nb = 0;
    for (int i = 0; i < n_in; ++i) {
        const float* p = (const float*)d_in[i];
        switch (in_sizes[i]) {
            case 13107200: x0 = p; break;
            case 6553600:  x1 = p; break;
            case 3276800:  x2 = p; break;
            case 68352:    w0 = p; break;
            case 136704:   w1 = p; break;
            case 273408:   w2 = p; break;
            case 267:      if (nb < 3) bs[nb++] = p; break;
            default: break;
        }
    }
    const int dyn = DYN_WORDS * 4;  // ~57.9 KB
    cudaFuncSetAttribute(detect_mma, cudaFuncAttributeMaxDynamicSharedMemorySize, dyn);
    dim3 grid(67, 3, 8);
    detect_mma<<<grid, NTH, dyn>>>(x0, w0, bs[0], x1, w1, bs[1], x2, w2, bs[2], (float*)d_out);
}

// round 7
// speedup vs baseline: 2.7481x; 1.0107x over previous
#include <cuda_runtime.h>
#include <cuda_bf16.h>
#include <cstdint>

#define NTH 256
#define STAGES 5

// ---------------- scratch (device globals; allocation-free) ----------------
// XT layout per level: [bat][n][k] bf16, k contiguous.
// offsets: L0 @0 (8*6400*256=13107200), L1 @13107200 (8*1600*512=6553600),
//          L2 @19660800 (8*400*1024=3276800). total 22937600
__device__ __nv_bfloat16 g_xt[22937600];
// W bf16: w0 @0 (68352), w1 @68352 (136704), w2 @205056 (273408). total 478464
__device__ __nv_bfloat16 g_wb[478464];

__constant__ float g_anch[3][6] = {
    {10.f, 13.f, 16.f, 30.f, 33.f, 23.f},
    {30.f, 61.f, 62.f, 45.f, 59.f, 119.f},
    {116.f, 90.f, 156.f, 198.f, 373.f, 326.f}
};

__device__ __forceinline__ float sigm(float x) { return 1.f / (1.f + __expf(-x)); }

__device__ __forceinline__ void mma_bf16(float* c, const uint32_t* a, const uint32_t* b) {
    asm volatile(
        "mma.sync.aligned.m16n8k16.row.col.f32.bf16.bf16.f32 "
        "{%0,%1,%2,%3}, {%4,%5,%6,%7}, {%8,%9}, {%0,%1,%2,%3};"
        : "+f"(c[0]), "+f"(c[1]), "+f"(c[2]), "+f"(c[3])
        : "r"(a[0]), "r"(a[1]), "r"(a[2]), "r"(a[3]), "r"(b[0]), "r"(b[1]));
}

__device__ __forceinline__ void cp16(uint32_t saddr, const void* gptr, uint32_t sz) {
    asm volatile("cp.async.cg.shared.global [%0], [%1], 16, %2;"
                 :: "r"(saddr), "l"(gptr), "r"(sz) : "memory");
}
#define CP_COMMIT() asm volatile("cp.async.commit_group;" ::: "memory")
#define CP_WAIT()   asm volatile("cp.async.wait_group %0;" :: "n"(STAGES - 2) : "memory")

// per-row word stride 20 -> (20*g + t4) mod 32 covers all banks (conflict-free LDS)
#define ROW_STRIDE 20
#define WS_WORDS (128 * ROW_STRIDE)   // 2560 words (128 m-rows x 32 halves + pad)
#define BS_WORDS (128 * ROW_STRIDE)   // 2560 words (128 n-rows x 32 halves + pad)
#define STAGE_WORDS (WS_WORDS + BS_WORDS)
#define DYN_WORDS (STAGES * STAGE_WORDS + 268)

// ---------------- convert kernels ----------------
__global__ void convert_w(const float* __restrict__ w0, const float* __restrict__ w1,
                          const float* __restrict__ w2)
{
    int i = blockIdx.x * 256 + threadIdx.x;
    if (i < 68352)        g_wb[i] = __float2bfloat16(w0[i]);
    else if (i < 205056)  g_wb[i] = __float2bfloat16(w1[i - 68352]);
    else if (i < 478464)  g_wb[i] = __float2bfloat16(w2[i - 205056]);
}

template<int C, int HW>
__global__ void transpose_x(const float* __restrict__ X, __nv_bfloat16* __restrict__ XT)
{
    __shared__ float t[32][33];
    const int n0 = blockIdx.x * 32, k0 = blockIdx.y * 32, bat = blockIdx.z;
    const int tx = threadIdx.x, ty = threadIdx.y;
    const float* Xb = X + (size_t)bat * C * HW;
#pragma unroll
    for (int r = 0; r < 32; r += 8) {
        const int n = n0 + tx;
        t[ty + r][tx] = (n < HW) ? Xb[(size_t)(k0 + ty + r) * HW + n] : 0.f;
    }
    __syncthreads();
    __nv_bfloat16* XTb = XT + (size_t)bat * HW * C;
#pragma unroll
    for (int r = 0; r < 32; r += 8) {
        const int n = n0 + ty + r;
        if (n < HW) XTb[(size_t)n * C + k0 + tx] = __float2bfloat16(t[tx][ty + r]);
    }
}

// ---------------- GEMM + decode ----------------
template<int C, int HW, int NX>
__device__ __forceinline__ void run_level(
    const __nv_bfloat16* __restrict__ XT, const __nv_bfloat16* __restrict__ Wb,
    const float* __restrict__ Bias, float* __restrict__ Out,
    int bat, int mt, int nt, float stride_px, int lvl, int loff)
{
    extern __shared__ uint32_t sh[];
    float* sBias = (float*)(sh + STAGES * STAGE_WORDS);

    const int tid  = threadIdx.x;
    const int wid  = tid >> 5;
    const int lane = tid & 31;
    const int g    = lane >> 2;
    const int t4   = lane & 3;
    const int wm   = (wid & 1) * 64;
    const int wn   = (wid >> 1) * 32;
    const int m0   = mt * 128;
    const int n0   = nt * 128;
    const __nv_bfloat16* XTb = XT + (size_t)bat * HW * C;

    for (int i = tid; i < 267; i += NTH) sBias[i] = Bias[i];

    // loader: row = tid>>1 (0..127), khalf = (tid&1)*16 (+8 for second cp)
    const int lRow  = tid >> 1;
    const int lKh   = (tid & 1) * 16;                 // half offset within 32-half chunk
    const uint32_t wSz = ((m0 + lRow) < 267) ? 16u : 0u;
    const uint32_t xSz = ((n0 + lRow) < HW) ? 16u : 0u;
    const __nv_bfloat16* wpB = Wb + (size_t)((m0 + lRow) < 267 ? (m0 + lRow) : 0) * C + lKh;
    const __nv_bfloat16* xpB = XTb + (size_t)((n0 + lRow) < HW ? (n0 + lRow) : 0) * C + lKh;

    uint32_t wsA[STAGES], bsA[STAGES];
#pragma unroll
    for (int s = 0; s < STAGES; ++s) {
        wsA[s] = (uint32_t)__cvta_generic_to_shared(sh + s * STAGE_WORDS + lRow * ROW_STRIDE + (lKh >> 1));
        bsA[s] = (uint32_t)__cvta_generic_to_shared(sh + s * STAGE_WORDS + WS_WORDS + lRow * ROW_STRIDE + (lKh >> 1));
    }

    const int NCH = C / 32;
    // prologue: chunks 0..STAGES-2
#pragma unroll
    for (int s = 0; s < STAGES - 1; ++s) {
        cp16(wsA[s],      wpB + (size_t)s * 32, wSz);
        cp16(wsA[s] + 16, wpB + (size_t)s * 32 + 8, wSz);
        cp16(bsA[s],      xpB + (size_t)s * 32, xSz);
        cp16(bsA[s] + 16, xpB + (size_t)s * 32 + 8, xSz);
        CP_COMMIT();
    }

    float acc[4][4][4];
#pragma unroll
    for (int a = 0; a < 4; ++a)
#pragma unroll
        for (int b = 0; b < 4; ++b)
#pragma unroll
            for (int k = 0; k < 4; ++k) acc[a][b][k] = 0.f;

    int s = 0;
    for (int i = 0; i < NCH; ++i) {
        CP_WAIT();
        __syncthreads();

        const uint32_t* Wst = sh + s * STAGE_WORDS;
        const uint32_t* Bst = Wst + WS_WORDS;

        // issue chunk i+STAGES-1 into the slot chunk i-1 just vacated
        const int ch = i + STAGES - 1;
        const int sn = (s + STAGES - 1 >= STAGES) ? s - 1 : s + STAGES - 1;
        if (ch < NCH) {
            cp16(wsA[sn],      wpB + (size_t)ch * 32, wSz);
            cp16(wsA[sn] + 16, wpB + (size_t)ch * 32 + 8, wSz);
            cp16(bsA[sn],      xpB + (size_t)ch * 32, xSz);
            cp16(bsA[sn] + 16, xpB + (size_t)ch * 32 + 8, xSz);
        }
        CP_COMMIT();

#pragma unroll
        for (int kk = 0; kk < 2; ++kk) {            // two k16 steps per 32-half chunk
            const int kw = kk * 8;                  // word offset within row
            uint32_t afr[4][4];
#pragma unroll
            for (int ma = 0; ma < 4; ++ma) {
                const int mr = wm + ma * 16 + g;
                afr[ma][0] = Wst[mr * ROW_STRIDE + kw + t4];
                afr[ma][1] = Wst[(mr + 8) * ROW_STRIDE + kw + t4];
                afr[ma][2] = Wst[mr * ROW_STRIDE + kw + t4 + 4];
                afr[ma][3] = Wst[(mr + 8) * ROW_STRIDE + kw + t4 + 4];
            }
            uint32_t bfr[4][2];
#pragma unroll
            for (int na = 0; na < 4; ++na) {
                const int nr = wn + na * 8 + g;
                bfr[na][0] = Bst[nr * ROW_STRIDE + kw + t4];
                bfr[na][1] = Bst[nr * ROW_STRIDE + kw + t4 + 4];
            }
#pragma unroll
            for (int ma = 0; ma < 4; ++ma)
#pragma unroll
                for (int na = 0; na < 4; ++na)
                    mma_bf16(acc[ma][na], afr[ma], bfr[na]);
        }
        s = (s + 1 == STAGES) ? 0 : s + 1;
    }

    // ---- fused decode epilogue ----
#pragma unroll
    for (int ma = 0; ma < 4; ++ma) {
#pragma unroll
        for (int half = 0; half < 2; ++half) {
            const int m = m0 + wm + ma * 16 + g + half * 8;
            if (m >= 267) continue;
            const int ai = m / 89;
            const int e  = m - ai * 89;
            const float bv = sBias[m];
            const float anc = (e == 2) ? g_anch[lvl][ai * 2]
                            : (e == 3) ? g_anch[lvl][ai * 2 + 1] : 0.f;
            const size_t rowbase = (size_t)bat * 25200 + (size_t)loff + (size_t)ai * HW;
#pragma unroll
            for (int na = 0; na < 4; ++na) {
#pragma unroll
                for (int c = 0; c < 2; ++c) {
                    const int n = n0 + wn + na * 8 + t4 * 2 + c;
                    if (HW % 128 != 0) { if (n >= HW) continue; }
                    const float v = acc[ma][na][half * 2 + c] + bv;
                    float res;
                    if (e == 0)      res = (sigm(v) + (float)(n % NX)) * stride_px;
                    else if (e == 1) res = (sigm(v) + (float)(n / NX)) * stride_px;
                    else if (e < 4)  res = __expf(v) * anc;
                    else             res = sigm(v);
                    Out[(rowbase + (size_t)n) * 89 + e] = res;
                }
            }
        }
    }
}

// N tiles: L0 50, L1 13 (last partial), L2 4 (last partial) -> 67
__global__ void __launch_bounds__(NTH, 2)
detect_mma(const float* __restrict__ b0, const float* __restrict__ b1,
           const float* __restrict__ b2, float* __restrict__ out)
{
    const int xt  = blockIdx.x;
    const int mt  = blockIdx.y;
    const int bat = blockIdx.z;

    if (xt < 50)
        run_level<256, 6400, 80>(g_xt, g_wb, b0, out, bat, mt, xt, 8.f, 0, 0);
    else if (xt < 63)
        run_level<512, 1600, 40>(g_xt + 13107200, g_wb + 68352, b1, out, bat, mt, xt - 50, 16.f, 1, 19200);
    else
        run_level<1024, 400, 20>(g_xt + 19660800, g_wb + 205056, b2, out, bat, mt, xt - 63, 32.f, 2, 24000);
}

extern "C" void kernel_launch(void* const* d_in, const int* in_sizes, int n_in,
                              void* d_out, int out_size)
{
    const float *x0 = 0, *x1 = 0, *x2 = 0, *w0 = 0, *w1 = 0, *w2 = 0;
    const float* bs[3] = {0, 0, 0};
    int nb = 0;
    for (int i = 0; i < n_in; ++i) {
        const float* p = (const float*)d_in[i];
        switch (in_sizes[i]) {
            case 13107200: x0 = p; break;
            case 6553600:  x1 = p; break;
            case 3276800:  x2 = p; break;
            case 68352:    w0 = p; break;
            case 136704:   w1 = p; break;
            case 273408:   w2 = p; break;
            case 267:      if (nb < 3) bs[nb++] = p; break;
            default: break;
        }
    }

    __nv_bfloat16* xt_ptr = 0;
    __nv_bfloat16* wb_ptr = 0;
    cudaGetSymbolAddress((void**)&xt_ptr, g_xt);
    cudaGetSymbolAddress((void**)&wb_ptr, g_wb);

    // convert passes
    convert_w<<<(478464 + 255) / 256, 256>>>(w0, w1, w2);
    {
        dim3 b(32, 8);
        transpose_x<256, 6400><<<dim3(200, 8, 8), b>>>(x0, xt_ptr);
        transpose_x<512, 1600><<<dim3(50, 16, 8), b>>>(x1, xt_ptr + 13107200);
        transpose_x<1024, 400><<<dim3(13, 32, 8), b>>>(x2, xt_ptr + 19660800);
    }

    const int dyn = DYN_WORDS * 4;  // ~103.5 KB
    cudaFuncSetAttribute(detect_mma, cudaFuncAttributeMaxDynamicSharedMemorySize, dyn);
    dim3 grid(67, 3, 8);
    detect_mma<<<grid, NTH, dyn>>>(bs[0], bs[1], bs[2], (float*)d_out);
}